// round 14
// baseline (speedup 1.0000x reference)
#include <cuda_runtime.h>
#include <cuda_fp16.h>
#include <math.h>
#include <stdint.h>

#define T 4096
#define D 1024
#define HDIM 4096
#define E 8
#define BM 256
#define BN 128
#define BK 64                 // 64 halves = 128B A-rows
#define STAGES 4
#define STAGE_BYTES 49152     // A 32KB + B 16KB
#define SMEM_DYN (STAGES * STAGE_BYTES)
#define MAXTILES 48
#define N1PER (HDIM / BN)     // 32 GEMM1 n-tiles per row
#define N2PER (D / BN)        // 8  GEMM2 n-tiles per row

// ---------------- scratch (device globals) ----------------
__device__ int    g_counts[E];
__device__ int    g_offsets[E];
__device__ int    g_cursor[E];
__device__ int    g_tok_e[2 * T];
__device__ float  g_tok_w[2 * T];
__device__ int    g_pair_token[2 * T];
__device__ float  g_pair_w[2 * T];
__device__ float  g_probs[T * E];
__device__ int    g_tile_e[MAXTILES];
__device__ int    g_tile_m0[MAXTILES];
__device__ int    g_ntiles;
__device__ int    g_work;                  // persistent work counter
__device__ int    g_row_done[MAXTILES];    // per tile-row: GEMM1 n-tiles completed
__device__ __half g_xa[(2 * T + 256) * D];                   // gathered x (fp16)
__device__ __half g_h[(size_t)(2 * T + 256) * HDIM];         // gelu output (fp16)

// ---------------- PTX helpers ----------------
__device__ __forceinline__ uint32_t smem_u32(const void* p) {
    uint32_t a;
    asm("{ .reg .u64 t; cvta.to.shared.u64 t, %1; cvt.u32.u64 %0, t; }" : "=r"(a) : "l"(p));
    return a;
}

#define CP_ASYNC16(saddr, gptr) \
    asm volatile("cp.async.cg.shared.global [%0], [%1], 16;" :: "r"(saddr), "l"(gptr) : "memory")
#define CP_COMMIT() asm volatile("cp.async.commit_group;" ::: "memory")
#define CP_WAIT(n)  asm volatile("cp.async.wait_group %0;" :: "n"(n) : "memory")

#define LDSM_X4(r0, r1, r2, r3, addr) \
    asm volatile("ldmatrix.sync.aligned.m8n8.x4.shared.b16 {%0,%1,%2,%3}, [%4];" \
        : "=r"(r0), "=r"(r1), "=r"(r2), "=r"(r3) : "r"(addr))

#define LDSM_X4_T(r0, r1, r2, r3, addr) \
    asm volatile("ldmatrix.sync.aligned.m8n8.x4.trans.shared.b16 {%0,%1,%2,%3}, [%4];" \
        : "=r"(r0), "=r"(r1), "=r"(r2), "=r"(r3) : "r"(addr))

#define MMA_F16(d, a, b0, b1) \
    asm volatile("mma.sync.aligned.m16n8k16.row.col.f32.f16.f16.f32 " \
        "{%0,%1,%2,%3}, {%4,%5,%6,%7}, {%8,%9}, {%0,%1,%2,%3};" \
        : "+f"((d)[0]), "+f"((d)[1]), "+f"((d)[2]), "+f"((d)[3]) \
        : "r"((a)[0]), "r"((a)[1]), "r"((a)[2]), "r"((a)[3]), "r"(b0), "r"(b1))

#define STS128(addr, u0, u1, u2, u3) \
    asm volatile("st.shared.v4.b32 [%0], {%1,%2,%3,%4};" \
        :: "r"(addr), "r"(u0), "r"(u1), "r"(u2), "r"(u3) : "memory")

__device__ __forceinline__ uint32_t swz(uint32_t off) {
    return off ^ ((off >> 3) & 0x70);
}
__device__ __forceinline__ uint32_t h2u(__half2 h) {
    return *reinterpret_cast<uint32_t*>(&h);
}

// fast gelu (tanh form): MUFU.EX2 + MUFU.RCP via __fdividef
__device__ __forceinline__ float gelu_tanh(float v) {
    float c = 0.7978845608028654f * (v + 0.044715f * v * v * v);
    float t = __expf(-2.0f * fabsf(c));
    float th = __fdividef(1.0f - t, 1.0f + t);
    th = copysignf(th, c);
    return 0.5f * v * (1.0f + th);
}

// ---------------- zero + init ----------------
__global__ __launch_bounds__(256) void zero_init_kernel(float* __restrict__ out) {
    size_t i = ((size_t)blockIdx.x * 256 + threadIdx.x) * 4;
    float4 z = {0.0f, 0.0f, 0.0f, 0.0f};
    *(float4*)(out + i) = z;
    if (blockIdx.x == 0) {
        if (threadIdx.x < E) g_counts[threadIdx.x] = 0;
        if (threadIdx.x == 0) g_work = 0;
        if (threadIdx.x < MAXTILES) g_row_done[threadIdx.x] = 0;
    }
}

// ---------------- router ----------------
__global__ __launch_bounds__(256) void router_kernel(const float* __restrict__ x,
                                                     const float* __restrict__ wg) {
    __shared__ float ws[E * D];
    for (int i = threadIdx.x; i < E * D; i += 256) ws[i] = wg[i];
    __syncthreads();
    int warp = threadIdx.x >> 5, lane = threadIdx.x & 31;
    int t = blockIdx.x * 8 + warp;
    float p[E];
#pragma unroll
    for (int e = 0; e < E; e++) p[e] = 0.0f;
    const float* xr = x + (size_t)t * D;
    for (int i = lane; i < D; i += 32) {
        float xv = xr[i];
#pragma unroll
        for (int e = 0; e < E; e++) p[e] += xv * ws[e * D + i];
    }
#pragma unroll
    for (int e = 0; e < E; e++)
#pragma unroll
        for (int off = 16; off > 0; off >>= 1)
            p[e] += __shfl_down_sync(0xffffffffu, p[e], off);
    if (lane == 0) {
        float mx = p[0];
#pragma unroll
        for (int e = 1; e < E; e++) mx = fmaxf(mx, p[e]);
        float ex[E], s = 0.0f;
#pragma unroll
        for (int e = 0; e < E; e++) { ex[e] = expf(p[e] - mx); s += ex[e]; }
        float inv = 1.0f / s;
#pragma unroll
        for (int e = 0; e < E; e++) g_probs[t * E + e] = ex[e] * inv;
        int i0 = 0;
#pragma unroll
        for (int e = 1; e < E; e++) if (p[e] > p[i0]) i0 = e;
        int i1 = (i0 == 0) ? 1 : 0;
#pragma unroll
        for (int e = 0; e < E; e++) if (e != i0 && p[e] > p[i1]) i1 = e;
        float w0 = 1.0f / (1.0f + expf(p[i1] - p[i0]));
        g_tok_e[2 * t] = i0;  g_tok_e[2 * t + 1] = i1;
        g_tok_w[2 * t] = w0;  g_tok_w[2 * t + 1] = 1.0f - w0;
        atomicAdd(&g_counts[i0], 1);
        atomicAdd(&g_counts[i1], 1);
    }
}

// ---------------- setup (aux + offsets + tile list) ----------------
__global__ __launch_bounds__(256) void setup_kernel(float* __restrict__ d_out, int out_size) {
    int tid = threadIdx.x;
    float gs[E], ps[E];
#pragma unroll
    for (int e = 0; e < E; e++) { gs[e] = 0.0f; ps[e] = 0.0f; }
    for (int t = tid; t < T; t += 256) {
        gs[g_tok_e[2 * t]]     += g_tok_w[2 * t];
        gs[g_tok_e[2 * t + 1]] += g_tok_w[2 * t + 1];
#pragma unroll
        for (int e = 0; e < E; e++) ps[e] += g_probs[t * E + e];
    }
    __shared__ float red[256];
    __shared__ float gsum[E], psum[E];
    for (int e = 0; e < E; e++) {
        red[tid] = gs[e]; __syncthreads();
        for (int s = 128; s > 0; s >>= 1) { if (tid < s) red[tid] += red[tid + s]; __syncthreads(); }
        if (tid == 0) gsum[e] = red[0];
        __syncthreads();
    }
    for (int e = 0; e < E; e++) {
        red[tid] = ps[e]; __syncthreads();
        for (int s = 128; s > 0; s >>= 1) { if (tid < s) red[tid] += red[tid + s]; __syncthreads(); }
        if (tid == 0) psum[e] = red[0];
        __syncthreads();
    }
    if (tid == 0) {
        float aux = 0.0f;
        for (int e = 0; e < E; e++) aux += (gsum[e] / (float)T) * (psum[e] / (float)T);
        aux *= (float)E;
        if (out_size > T * D) d_out[T * D] = aux;
        int off = 0, nt = 0;
        for (int e = 0; e < E; e++) {
            g_offsets[e] = off;
            for (int m0 = 0; m0 < g_counts[e]; m0 += BM) { g_tile_e[nt] = e; g_tile_m0[nt] = m0; nt++; }
            off += g_counts[e];
            g_cursor[e] = 0;
        }
        g_ntiles = nt;
    }
}

// ---------------- fused scatter + gather ----------------
__global__ __launch_bounds__(256) void scatter_gather_kernel(const float* __restrict__ x) {
    int t = blockIdx.x;
    __shared__ int sp[2];
    if (threadIdx.x < 2) {
        int e = g_tok_e[2 * t + threadIdx.x];
        int p = g_offsets[e] + atomicAdd(&g_cursor[e], 1);
        g_pair_token[p] = t;
        g_pair_w[p] = g_tok_w[2 * t + threadIdx.x];
        sp[threadIdx.x] = p;
    }
    __syncthreads();
    int p0 = sp[0], p1 = sp[1];
    int c = threadIdx.x * 4;
    float4 v = *(const float4*)(x + (size_t)t * D + c);
    __half2 h0 = __floats2half2_rn(v.x, v.y);
    __half2 h1 = __floats2half2_rn(v.z, v.w);
    uint2 u;
    u.x = h2u(h0);
    u.y = h2u(h1);
    *reinterpret_cast<uint2*>(g_xa + (size_t)p0 * D + c) = u;
    *reinterpret_cast<uint2*>(g_xa + (size_t)p1 * D + c) = u;
}

// ---------------- one 256x128 GEMM tile (proven R11 body) ----------------
template<int KTOT, int NTOT, bool GELU, bool ATOMIC, typename OutT>
__device__ void gemm_tile(const __half* __restrict__ Aall, const float* __restrict__ Bg,
                          const float* __restrict__ bias, OutT* __restrict__ Out,
                          int ty, int n0, uint32_t sbase)
{
    int e = g_tile_e[ty];
    int m0 = g_tile_m0[ty];
    int cnt = g_counts[e];
    int base = g_offsets[e];

    int tid = threadIdx.x;
    int wid = tid >> 5, lane = tid & 31;
    int warp_m = wid >> 1, warp_n = wid & 1;
    int m_base = warp_m * 64, n_base = warp_n * 64;

    const __half* Abase = Aall + (size_t)(base + m0) * KTOT;
    const float* Bbase = Bg + (size_t)e * KTOT * NTOT + n0;

    int bch_r[4], bch_cc[4];
    const float* bch_g[4];
#pragma unroll
    for (int j = 0; j < 4; j++) {
        int chunk = tid + 256 * j;
        int r = chunk >> 3, cc = chunk & 7;
        bch_r[j] = r; bch_cc[j] = cc;
        int nh = r >> 6, k = r & 63;
        bch_g[j] = Bbase + (size_t)k * NTOT + nh * 64 + cc * 8;
    }

    float4 breg0[4], breg1[4];

#define LDG_B(kit) do { \
        size_t koff_ = (size_t)(kit) * BK * NTOT; \
        _Pragma("unroll") \
        for (int j_ = 0; j_ < 4; j_++) { \
            const float* gp_ = bch_g[j_] + koff_; \
            breg0[j_] = *(const float4*)gp_; \
            breg1[j_] = *(const float4*)(gp_ + 4); \
        } \
    } while (0)

#define STS_B(s) do { \
        uint32_t b_sm_ = sbase + (uint32_t)(s) * STAGE_BYTES + 32768; \
        _Pragma("unroll") \
        for (int j_ = 0; j_ < 4; j_++) { \
            uint32_t off_ = (uint32_t)(bch_r[j_] * 128 + bch_cc[j_] * 16); \
            uint32_t u0_ = h2u(__floats2half2_rn(breg0[j_].x, breg0[j_].y)); \
            uint32_t u1_ = h2u(__floats2half2_rn(breg0[j_].z, breg0[j_].w)); \
            uint32_t u2_ = h2u(__floats2half2_rn(breg1[j_].x, breg1[j_].y)); \
            uint32_t u3_ = h2u(__floats2half2_rn(breg1[j_].z, breg1[j_].w)); \
            STS128(b_sm_ + swz(off_), u0_, u1_, u2_, u3_); \
        } \
    } while (0)

#define LOAD_A(s, it) do { \
        uint32_t a_sm_ = sbase + (uint32_t)(s) * STAGE_BYTES; \
        int k0_ = (it) * BK; \
        _Pragma("unroll") \
        for (int j_ = 0; j_ < 8; j_++) { \
            int chunk_ = tid + 256 * j_; \
            int row_ = chunk_ >> 3, cc_ = chunk_ & 7; \
            uint32_t off_ = (uint32_t)(row_ * 128 + cc_ * 16); \
            CP_ASYNC16(a_sm_ + swz(off_), Abase + (size_t)row_ * KTOT + k0_ + cc_ * 8); \
        } \
    } while (0)

    float acc[4][8][4];
#pragma unroll
    for (int i = 0; i < 4; i++)
#pragma unroll
        for (int j = 0; j < 8; j++)
#pragma unroll
            for (int k = 0; k < 4; k++) acc[i][j][k] = 0.0f;

    const int KITERS = KTOT / BK;

#pragma unroll
    for (int s = 0; s < STAGES - 1; s++) {
        LDG_B(s);
        STS_B(s);
        LOAD_A(s, s);
        CP_COMMIT();
    }
    LDG_B(STAGES - 1);

    int gq = lane >> 3, l7 = lane & 7;
    uint32_t soffB[4];
#pragma unroll
    for (int np = 0; np < 4; np++) {
        int nl = n_base + np * 16 + (gq & 1) * 8;
        int klow = (gq >> 1) * 8 + l7;
        uint32_t boff = (uint32_t)((((nl >> 6) * 64) + klow) * 128 + (nl & 63) * 2);
        soffB[np] = swz(boff);
    }

    int lrow = lane & 15;
    uint32_t lkhi = (uint32_t)((lane >> 4) * 16);

    for (int it = 0; it < KITERS; ++it) {
        CP_WAIT(STAGES - 2);
        __syncthreads();

        int refill = it + STAGES - 1;
        if (refill < KITERS) {
            int rs = refill % STAGES;
            STS_B(rs);
            LOAD_A(rs, refill);
        }
        CP_COMMIT();
        if (it + STAGES < KITERS) LDG_B(it + STAGES);

        uint32_t a_sm = sbase + (uint32_t)(it % STAGES) * STAGE_BYTES;
        uint32_t b_sm = a_sm + 32768;

#pragma unroll
        for (int ks = 0; ks < 4; ks++) {
            uint32_t a[4][4], b[4][4];
#pragma unroll
            for (int mt = 0; mt < 4; mt++) {
                uint32_t off = (uint32_t)((m_base + mt * 16 + lrow) * 128) + ks * 32 + lkhi;
                LDSM_X4(a[mt][0], a[mt][1], a[mt][2], a[mt][3], a_sm + swz(off));
            }
#pragma unroll
            for (int np = 0; np < 4; np++) {
                LDSM_X4_T(b[np][0], b[np][1], b[np][2], b[np][3],
                          b_sm + soffB[np] + (uint32_t)(ks * 2048));
            }
#pragma unroll
            for (int mt = 0; mt < 4; mt++)
#pragma unroll
                for (int nt = 0; nt < 8; nt++)
                    MMA_F16(acc[mt][nt], a[mt], b[nt >> 1][nt & 1], b[nt >> 1][(nt & 1) + 2]);
        }
    }

    // epilogue
    int rq = lane >> 2;
    int cq = (lane & 3) * 2;
#pragma unroll
    for (int mt = 0; mt < 4; mt++) {
#pragma unroll
        for (int h = 0; h < 2; h++) {
            int row = m_base + mt * 16 + h * 8 + rq;
            int m = m0 + row;
            if (m >= cnt) continue;
            if (ATOMIC) {
                int P = base + m;
                int tok = g_pair_token[P];
                float w = g_pair_w[P];
                float* orow = (float*)Out + (size_t)tok * NTOT;
                const float* bp = bias + (size_t)e * NTOT;
#pragma unroll
                for (int nt = 0; nt < 8; nt++) {
                    int col = n0 + n_base + nt * 8 + cq;
                    atomicAdd(&orow[col],     w * (acc[mt][nt][h * 2 + 0] + bp[col]));
                    atomicAdd(&orow[col + 1], w * (acc[mt][nt][h * 2 + 1] + bp[col + 1]));
                }
            } else {
                OutT* orow = Out + (size_t)(base + m) * NTOT + n0;
#pragma unroll
                for (int nt = 0; nt < 8; nt++) {
                    int col = n_base + nt * 8 + cq;
                    float v0 = acc[mt][nt][h * 2 + 0];
                    float v1 = acc[mt][nt][h * 2 + 1];
                    if (GELU) {
                        const float* bp = bias + (size_t)e * NTOT + n0 + col;
                        v0 = gelu_tanh(v0 + bp[0]);
                        v1 = gelu_tanh(v1 + bp[1]);
                    }
                    __half2 hv = __floats2half2_rn(v0, v1);
                    *reinterpret_cast<__half2*>((__half*)orow + col) = hv;
                }
            }
        }
    }
#undef LDG_B
#undef STS_B
#undef LOAD_A
}

// ---------------- persistent fused GEMM1+GEMM2 ----------------
// Work items: [0, 32*nt) = GEMM1 tiles (row-major: ty = w/32, n-tile = w%32).
// [32*nt, 32*nt + 8*nt) = GEMM2 tiles gated on g_row_done[ty] == 32.
__global__ __launch_bounds__(256, 1) void moe_persistent_kernel(
    const __half* __restrict__ xa, const float* __restrict__ W1,
    const float* __restrict__ b1, __half* __restrict__ gh,
    const float* __restrict__ W2, const float* __restrict__ b2,
    float* __restrict__ out)
{
    extern __shared__ char sm[];
    uint32_t sbase = smem_u32(sm);
    __shared__ int s_w;
    const int nt = g_ntiles;
    const int n1 = nt * N1PER;
    const int ntotal = n1 + nt * N2PER;

    for (;;) {
        __syncthreads();                  // smem reuse barrier between items
        if (threadIdx.x == 0) s_w = atomicAdd(&g_work, 1);
        __syncthreads();
        int w = s_w;
        if (w >= ntotal) return;

        if (w < n1) {
            int tyi = w >> 5;             // N1PER = 32
            int n0 = (w & 31) * BN;
            gemm_tile<D, HDIM, true, false, __half>(xa, W1, b1, gh, tyi, n0, sbase);
            __threadfence();              // release g_h writes
            __syncthreads();
            if (threadIdx.x == 0) atomicAdd(&g_row_done[tyi], 1);
        } else {
            int w2 = w - n1;
            int tyi = w2 >> 3;            // N2PER = 8
            int n0 = (w2 & 7) * BN;
            if (threadIdx.x == 0) {
                volatile int* flag = g_row_done + tyi;
                while (*flag < N1PER) __nanosleep(200);
            }
            __syncthreads();
            __threadfence();              // acquire g_h writes
            gemm_tile<HDIM, D, false, true, float>(gh, W2, b2, out, tyi, n0, sbase);
        }
    }
}

// ---------------- launch ----------------
extern "C" void kernel_launch(void* const* d_in, const int* in_sizes, int n_in,
                              void* d_out, int out_size) {
    const float* x  = (const float*)d_in[0];
    const float* wg = (const float*)d_in[1];
    const float* W1 = (const float*)d_in[2];
    const float* b1 = (const float*)d_in[3];
    const float* W2 = (const float*)d_in[4];
    const float* b2 = (const float*)d_in[5];
    float* out = (float*)d_out;

    cudaFuncSetAttribute(moe_persistent_kernel,
                         cudaFuncAttributeMaxDynamicSharedMemorySize, SMEM_DYN);

    __half* xa;  cudaGetSymbolAddress((void**)&xa, g_xa);
    __half* gh;  cudaGetSymbolAddress((void**)&gh, g_h);

    zero_init_kernel<<<(T * D / 4) / 256, 256>>>(out);
    router_kernel<<<T / 8, 256>>>(x, wg);
    setup_kernel<<<1, 256>>>(out, out_size);
    scatter_gather_kernel<<<T, 256>>>(x);
    moe_persistent_kernel<<<160, 256, SMEM_DYN>>>(xa, W1, b1, gh, W2, b2, out);
}

// round 15
// speedup vs baseline: 1.0892x; 1.0892x over previous
#include <cuda_runtime.h>
#include <cuda_fp16.h>
#include <math.h>
#include <stdint.h>

#define T 4096
#define D 1024
#define HDIM 4096
#define E 8
#define BM 256
#define BN 128
#define BK 64                 // 64 halves = 128B A-rows
#define STAGES 4
#define STAGE_BYTES 49152     // A 32KB + B 16KB
#define SMEM_DYN (STAGES * STAGE_BYTES)
#define MAXTILES 48

// ---------------- scratch (device globals) ----------------
__device__ int    g_counts[E];
__device__ int    g_offsets[E];
__device__ int    g_cursor[E];
__device__ int    g_tok_e[2 * T];
__device__ float  g_tok_w[2 * T];
__device__ int    g_pair_token[2 * T];
__device__ float  g_pair_w[2 * T];
__device__ float  g_probs[T * E];
__device__ int    g_tile_e[MAXTILES];
__device__ int    g_tile_m0[MAXTILES];
__device__ int    g_ntiles;
__device__ __half g_xa[(2 * T + 256) * D];                   // gathered x (fp16)
__device__ __half g_h[(size_t)(2 * T + 256) * HDIM];         // gelu output (fp16)

// ---------------- PTX helpers ----------------
__device__ __forceinline__ uint32_t smem_u32(const void* p) {
    uint32_t a;
    asm("{ .reg .u64 t; cvta.to.shared.u64 t, %1; cvt.u32.u64 %0, t; }" : "=r"(a) : "l"(p));
    return a;
}

#define CP_ASYNC16(saddr, gptr) \
    asm volatile("cp.async.cg.shared.global [%0], [%1], 16;" :: "r"(saddr), "l"(gptr) : "memory")
#define CP_COMMIT() asm volatile("cp.async.commit_group;" ::: "memory")
#define CP_WAIT(n)  asm volatile("cp.async.wait_group %0;" :: "n"(n) : "memory")

#define LDSM_X4(r0, r1, r2, r3, addr) \
    asm volatile("ldmatrix.sync.aligned.m8n8.x4.shared.b16 {%0,%1,%2,%3}, [%4];" \
        : "=r"(r0), "=r"(r1), "=r"(r2), "=r"(r3) : "r"(addr))

#define LDSM_X4_T(r0, r1, r2, r3, addr) \
    asm volatile("ldmatrix.sync.aligned.m8n8.x4.trans.shared.b16 {%0,%1,%2,%3}, [%4];" \
        : "=r"(r0), "=r"(r1), "=r"(r2), "=r"(r3) : "r"(addr))

#define MMA_F16(d, a, b0, b1) \
    asm volatile("mma.sync.aligned.m16n8k16.row.col.f32.f16.f16.f32 " \
        "{%0,%1,%2,%3}, {%4,%5,%6,%7}, {%8,%9}, {%0,%1,%2,%3};" \
        : "+f"((d)[0]), "+f"((d)[1]), "+f"((d)[2]), "+f"((d)[3]) \
        : "r"((a)[0]), "r"((a)[1]), "r"((a)[2]), "r"((a)[3]), "r"(b0), "r"(b1))

#define STS128(addr, u0, u1, u2, u3) \
    asm volatile("st.shared.v4.b32 [%0], {%1,%2,%3,%4};" \
        :: "r"(addr), "r"(u0), "r"(u1), "r"(u2), "r"(u3) : "memory")

__device__ __forceinline__ uint32_t swz(uint32_t off) {
    return off ^ ((off >> 3) & 0x70);
}
__device__ __forceinline__ uint32_t h2u(__half2 h) {
    return *reinterpret_cast<uint32_t*>(&h);
}

// fast gelu (tanh form): MUFU.EX2 + MUFU.RCP via __fdividef, ~10 instrs
__device__ __forceinline__ float gelu_tanh(float v) {
    float c = 0.7978845608028654f * (v + 0.044715f * v * v * v);
    float t = __expf(-2.0f * fabsf(c));
    float th = __fdividef(1.0f - t, 1.0f + t);
    th = copysignf(th, c);
    return 0.5f * v * (1.0f + th);
}

// ---------------- zero + init ----------------
__global__ __launch_bounds__(256) void zero_init_kernel(float* __restrict__ out) {
    size_t i = ((size_t)blockIdx.x * 256 + threadIdx.x) * 4;
    float4 z = {0.0f, 0.0f, 0.0f, 0.0f};
    *(float4*)(out + i) = z;
    if (blockIdx.x == 0 && threadIdx.x < E) g_counts[threadIdx.x] = 0;
}

// ---------------- router (float4-vectorized inner loop) ----------------
__global__ __launch_bounds__(256) void router_kernel(const float* __restrict__ x,
                                                     const float* __restrict__ wg) {
    __shared__ float ws[E * D];
    for (int i = threadIdx.x; i < E * D; i += 256) ws[i] = wg[i];
    __syncthreads();
    int warp = threadIdx.x >> 5, lane = threadIdx.x & 31;
    int t = blockIdx.x * 8 + warp;
    float p[E];
#pragma unroll
    for (int e = 0; e < E; e++) p[e] = 0.0f;
    const float* xr = x + (size_t)t * D;
#pragma unroll
    for (int i = lane * 4; i < D; i += 128) {
        float4 xv = *(const float4*)(xr + i);
#pragma unroll
        for (int e = 0; e < E; e++) {
            float4 wv = *(const float4*)(ws + e * D + i);
            p[e] += xv.x * wv.x + xv.y * wv.y + xv.z * wv.z + xv.w * wv.w;
        }
    }
#pragma unroll
    for (int e = 0; e < E; e++)
#pragma unroll
        for (int off = 16; off > 0; off >>= 1)
            p[e] += __shfl_down_sync(0xffffffffu, p[e], off);
    if (lane == 0) {
        float mx = p[0];
#pragma unroll
        for (int e = 1; e < E; e++) mx = fmaxf(mx, p[e]);
        float ex[E], s = 0.0f;
#pragma unroll
        for (int e = 0; e < E; e++) { ex[e] = expf(p[e] - mx); s += ex[e]; }
        float inv = 1.0f / s;
#pragma unroll
        for (int e = 0; e < E; e++) g_probs[t * E + e] = ex[e] * inv;
        int i0 = 0;
#pragma unroll
        for (int e = 1; e < E; e++) if (p[e] > p[i0]) i0 = e;
        int i1 = (i0 == 0) ? 1 : 0;
#pragma unroll
        for (int e = 0; e < E; e++) if (e != i0 && p[e] > p[i1]) i1 = e;
        float w0 = 1.0f / (1.0f + expf(p[i1] - p[i0]));
        g_tok_e[2 * t] = i0;  g_tok_e[2 * t + 1] = i1;
        g_tok_w[2 * t] = w0;  g_tok_w[2 * t + 1] = 1.0f - w0;
        atomicAdd(&g_counts[i0], 1);
        atomicAdd(&g_counts[i1], 1);
    }
}

// ---------------- setup (aux + offsets + tile list) ----------------
__global__ __launch_bounds__(256) void setup_kernel(float* __restrict__ d_out, int out_size) {
    int tid = threadIdx.x;
    float gs[E], ps[E];
#pragma unroll
    for (int e = 0; e < E; e++) { gs[e] = 0.0f; ps[e] = 0.0f; }
    for (int t = tid; t < T; t += 256) {
        gs[g_tok_e[2 * t]]     += g_tok_w[2 * t];
        gs[g_tok_e[2 * t + 1]] += g_tok_w[2 * t + 1];
#pragma unroll
        for (int e = 0; e < E; e++) ps[e] += g_probs[t * E + e];
    }
    __shared__ float red[256];
    __shared__ float gsum[E], psum[E];
    for (int e = 0; e < E; e++) {
        red[tid] = gs[e]; __syncthreads();
        for (int s = 128; s > 0; s >>= 1) { if (tid < s) red[tid] += red[tid + s]; __syncthreads(); }
        if (tid == 0) gsum[e] = red[0];
        __syncthreads();
    }
    for (int e = 0; e < E; e++) {
        red[tid] = ps[e]; __syncthreads();
        for (int s = 128; s > 0; s >>= 1) { if (tid < s) red[tid] += red[tid + s]; __syncthreads(); }
        if (tid == 0) psum[e] = red[0];
        __syncthreads();
    }
    if (tid == 0) {
        float aux = 0.0f;
        for (int e = 0; e < E; e++) aux += (gsum[e] / (float)T) * (psum[e] / (float)T);
        aux *= (float)E;
        if (out_size > T * D) d_out[T * D] = aux;
        int off = 0, nt = 0;
        for (int e = 0; e < E; e++) {
            g_offsets[e] = off;
            for (int m0 = 0; m0 < g_counts[e]; m0 += BM) { g_tile_e[nt] = e; g_tile_m0[nt] = m0; nt++; }
            off += g_counts[e];
            g_cursor[e] = 0;
        }
        g_ntiles = nt;
    }
}

// ---------------- fused scatter + gather ----------------
__global__ __launch_bounds__(256) void scatter_gather_kernel(const float* __restrict__ x) {
    int t = blockIdx.x;
    __shared__ int sp[2];
    if (threadIdx.x < 2) {
        int e = g_tok_e[2 * t + threadIdx.x];
        int p = g_offsets[e] + atomicAdd(&g_cursor[e], 1);
        g_pair_token[p] = t;
        g_pair_w[p] = g_tok_w[2 * t + threadIdx.x];
        sp[threadIdx.x] = p;
    }
    __syncthreads();
    int p0 = sp[0], p1 = sp[1];
    int c = threadIdx.x * 4;
    float4 v = *(const float4*)(x + (size_t)t * D + c);
    __half2 h0 = __floats2half2_rn(v.x, v.y);
    __half2 h1 = __floats2half2_rn(v.z, v.w);
    uint2 u;
    u.x = h2u(h0);
    u.y = h2u(h1);
    *reinterpret_cast<uint2*>(g_xa + (size_t)p0 * D + c) = u;
    *reinterpret_cast<uint2*>(g_xa + (size_t)p1 * D + c) = u;
}

// ---------------- fp16 mma.sync grouped GEMM, fp32-B converted in producer ----------------
// A: [pairs][KTOT] k-major fp16.  B: [E][KTOT][NTOT] fp32 (original weight layout).
// Smem B tile (BN=128): physical row = (n>=64)*64 + k (128 rows x 128B), ldmatrix.trans.
// CTA 256x128, BK=64, 4 stages: A via cp.async, B via LDG.128 staging + cvt + STS.
// 8 warps = 4m x 2n, warp tile 64x64.
template<int KTOT, int NTOT, bool GELU, bool ATOMIC, typename OutT>
__global__ __launch_bounds__(256, 1) void mma_gemm_kernel(
    const __half* __restrict__ Aall, const float* __restrict__ Bg,
    const float* __restrict__ bias, OutT* __restrict__ Out)
{
    int ty = blockIdx.y;
    if (ty >= g_ntiles) return;
    int e = g_tile_e[ty];
    int m0 = g_tile_m0[ty];
    int cnt = g_counts[e];
    int base = g_offsets[e];
    int n0 = blockIdx.x * BN;

    extern __shared__ char sm[];
    uint32_t sbase = smem_u32(sm);
    int tid = threadIdx.x;
    int wid = tid >> 5, lane = tid & 31;
    int warp_m = wid >> 1, warp_n = wid & 1;
    int m_base = warp_m * 64, n_base = warp_n * 64;

    const __half* Abase = Aall + (size_t)(base + m0) * KTOT;
    const float* Bbase = Bg + (size_t)e * KTOT * NTOT + n0;

    // B producer chunk mapping: 4 chunks/thread; chunk -> phys row r (0..127), 16B col cc
    int bch_r[4], bch_cc[4];
    const float* bch_g[4];
#pragma unroll
    for (int j = 0; j < 4; j++) {
        int chunk = tid + 256 * j;
        int r = chunk >> 3, cc = chunk & 7;
        bch_r[j] = r; bch_cc[j] = cc;
        int nh = r >> 6, k = r & 63;
        bch_g[j] = Bbase + (size_t)k * NTOT + nh * 64 + cc * 8;
    }

    float4 breg0[4], breg1[4];

#define LDG_B(kit) do { \
        size_t koff_ = (size_t)(kit) * BK * NTOT; \
        _Pragma("unroll") \
        for (int j_ = 0; j_ < 4; j_++) { \
            const float* gp_ = bch_g[j_] + koff_; \
            breg0[j_] = *(const float4*)gp_; \
            breg1[j_] = *(const float4*)(gp_ + 4); \
        } \
    } while (0)

#define STS_B(s) do { \
        uint32_t b_sm_ = sbase + (uint32_t)(s) * STAGE_BYTES + 32768; \
        _Pragma("unroll") \
        for (int j_ = 0; j_ < 4; j_++) { \
            uint32_t off_ = (uint32_t)(bch_r[j_] * 128 + bch_cc[j_] * 16); \
            uint32_t u0_ = h2u(__floats2half2_rn(breg0[j_].x, breg0[j_].y)); \
            uint32_t u1_ = h2u(__floats2half2_rn(breg0[j_].z, breg0[j_].w)); \
            uint32_t u2_ = h2u(__floats2half2_rn(breg1[j_].x, breg1[j_].y)); \
            uint32_t u3_ = h2u(__floats2half2_rn(breg1[j_].z, breg1[j_].w)); \
            STS128(b_sm_ + swz(off_), u0_, u1_, u2_, u3_); \
        } \
    } while (0)

#define LOAD_A(s, it) do { \
        uint32_t a_sm_ = sbase + (uint32_t)(s) * STAGE_BYTES; \
        int k0_ = (it) * BK; \
        _Pragma("unroll") \
        for (int j_ = 0; j_ < 8; j_++) { \
            int chunk_ = tid + 256 * j_; \
            int row_ = chunk_ >> 3, cc_ = chunk_ & 7; \
            uint32_t off_ = (uint32_t)(row_ * 128 + cc_ * 16); \
            CP_ASYNC16(a_sm_ + swz(off_), Abase + (size_t)row_ * KTOT + k0_ + cc_ * 8); \
        } \
    } while (0)

    float acc[4][8][4];
#pragma unroll
    for (int i = 0; i < 4; i++)
#pragma unroll
        for (int j = 0; j < 8; j++)
#pragma unroll
            for (int k = 0; k < 4; k++) acc[i][j][k] = 0.0f;

    const int KITERS = KTOT / BK;

    // prologue: fill stages 0..S-2 (B direct LDG+STS, A cp.async)
#pragma unroll
    for (int s = 0; s < STAGES - 1; s++) {
        LDG_B(s);
        STS_B(s);
        LOAD_A(s, s);
        CP_COMMIT();
    }
    // preload B regs for stage S-1 (stored at iter 0)
    LDG_B(STAGES - 1);

    // B ldmatrix.trans swizzled base offsets (per lane, per n16-block)
    int gq = lane >> 3, l7 = lane & 7;
    uint32_t soffB[4];
#pragma unroll
    for (int np = 0; np < 4; np++) {
        int nl = n_base + np * 16 + (gq & 1) * 8;
        int klow = (gq >> 1) * 8 + l7;
        uint32_t boff = (uint32_t)((((nl >> 6) * 64) + klow) * 128 + (nl & 63) * 2);
        soffB[np] = swz(boff);
    }

    int lrow = lane & 15;
    uint32_t lkhi = (uint32_t)((lane >> 4) * 16);

#pragma unroll 2
    for (int it = 0; it < KITERS; ++it) {
        CP_WAIT(STAGES - 2);
        __syncthreads();

        int refill = it + STAGES - 1;
        if (refill < KITERS) {
            int rs = refill % STAGES;
            STS_B(rs);
            LOAD_A(rs, refill);
        }
        CP_COMMIT();
        if (it + STAGES < KITERS) LDG_B(it + STAGES);

        uint32_t a_sm = sbase + (uint32_t)(it % STAGES) * STAGE_BYTES;
        uint32_t b_sm = a_sm + 32768;

#pragma unroll
        for (int ks = 0; ks < 4; ks++) {   // 4 x k16 per BK=64
            uint32_t a[4][4], b[4][4];
#pragma unroll
            for (int mt = 0; mt < 4; mt++) {
                uint32_t off = (uint32_t)((m_base + mt * 16 + lrow) * 128) + ks * 32 + lkhi;
                LDSM_X4(a[mt][0], a[mt][1], a[mt][2], a[mt][3], a_sm + swz(off));
            }
#pragma unroll
            for (int np = 0; np < 4; np++) {
                LDSM_X4_T(b[np][0], b[np][1], b[np][2], b[np][3],
                          b_sm + soffB[np] + (uint32_t)(ks * 2048));
            }
#pragma unroll
            for (int mt = 0; mt < 4; mt++)
#pragma unroll
                for (int nt = 0; nt < 8; nt++)
                    MMA_F16(acc[mt][nt], a[mt], b[nt >> 1][nt & 1], b[nt >> 1][(nt & 1) + 2]);
        }
    }

    // ---- epilogue ----
    int rq = lane >> 2;
    int cq = (lane & 3) * 2;
#pragma unroll
    for (int mt = 0; mt < 4; mt++) {
#pragma unroll
        for (int h = 0; h < 2; h++) {
            int row = m_base + mt * 16 + h * 8 + rq;
            int m = m0 + row;
            if (m >= cnt) continue;
            if (ATOMIC) {
                // GEMM2: y[tok] += w * (acc + b2[e])
                int P = base + m;
                int tok = g_pair_token[P];
                float w = g_pair_w[P];
                float* orow = (float*)Out + (size_t)tok * NTOT;
                const float* bp = bias + (size_t)e * NTOT;
#pragma unroll
                for (int nt = 0; nt < 8; nt++) {
                    int col = n0 + n_base + nt * 8 + cq;
                    atomicAdd(&orow[col],     w * (acc[mt][nt][h * 2 + 0] + bp[col]));
                    atomicAdd(&orow[col + 1], w * (acc[mt][nt][h * 2 + 1] + bp[col + 1]));
                }
            } else {
                OutT* orow = Out + (size_t)(base + m) * NTOT + n0;
#pragma unroll
                for (int nt = 0; nt < 8; nt++) {
                    int col = n_base + nt * 8 + cq;
                    float v0 = acc[mt][nt][h * 2 + 0];
                    float v1 = acc[mt][nt][h * 2 + 1];
                    if (GELU) {
                        const float* bp = bias + (size_t)e * NTOT + n0 + col;
                        v0 = gelu_tanh(v0 + bp[0]);
                        v1 = gelu_tanh(v1 + bp[1]);
                    }
                    __half2 hv = __floats2half2_rn(v0, v1);
                    *reinterpret_cast<__half2*>((__half*)orow + col) = hv;
                }
            }
        }
    }
#undef LDG_B
#undef STS_B
#undef LOAD_A
}

// ---------------- launch ----------------
extern "C" void kernel_launch(void* const* d_in, const int* in_sizes, int n_in,
                              void* d_out, int out_size) {
    const float* x  = (const float*)d_in[0];
    const float* wg = (const float*)d_in[1];
    const float* W1 = (const float*)d_in[2];
    const float* b1 = (const float*)d_in[3];
    const float* W2 = (const float*)d_in[4];
    const float* b2 = (const float*)d_in[5];
    float* out = (float*)d_out;

    cudaFuncSetAttribute(mma_gemm_kernel<D, HDIM, true, false, __half>,
                         cudaFuncAttributeMaxDynamicSharedMemorySize, SMEM_DYN);
    cudaFuncSetAttribute(mma_gemm_kernel<HDIM, D, false, true, float>,
                         cudaFuncAttributeMaxDynamicSharedMemorySize, SMEM_DYN);

    __half* xa;  cudaGetSymbolAddress((void**)&xa, g_xa);
    __half* gh;  cudaGetSymbolAddress((void**)&gh, g_h);

    zero_init_kernel<<<(T * D / 4) / 256, 256>>>(out);
    router_kernel<<<T / 8, 256>>>(x, wg);
    setup_kernel<<<1, 256>>>(out, out_size);
    scatter_gather_kernel<<<T, 256>>>(x);
    mma_gemm_kernel<D, HDIM, true, false, __half>
        <<<dim3(HDIM / BN, MAXTILES), 256, SMEM_DYN>>>(xa, W1, b1, gh);
    mma_gemm_kernel<HDIM, D, false, true, float>
        <<<dim3(D / BN, MAXTILES), 256, SMEM_DYN>>>(gh, W2, b2, out);
}

// round 16
// speedup vs baseline: 1.0956x; 1.0059x over previous
#include <cuda_runtime.h>
#include <cuda_fp16.h>
#include <math.h>
#include <stdint.h>

#define T 4096
#define D 1024
#define HDIM 4096
#define E 8
#define BM 256
#define BN 128
#define BK 64                 // 64 halves = 128B A-rows
#define STAGES 4
#define STAGE_BYTES 49152     // A 32KB + B 16KB
#define SMEM_DYN (STAGES * STAGE_BYTES)
#define MAXTILES 48

// ---------------- scratch (device globals) ----------------
__device__ int    g_counts[E];
__device__ int    g_offsets[E];
__device__ int    g_cursor[E];
__device__ int    g_tok_e[2 * T];
__device__ float  g_tok_w[2 * T];
__device__ int    g_pair_token[2 * T];
__device__ float  g_pair_w[2 * T];
__device__ float  g_probs[T * E];
__device__ int    g_tile_e[MAXTILES];
__device__ int    g_tile_m0[MAXTILES];
__device__ int    g_ntiles;
__device__ __half g_xa[(2 * T + 256) * D];                   // gathered x (fp16)
__device__ __half g_h[(size_t)(2 * T + 256) * HDIM];         // gelu output (fp16)

// ---------------- PTX helpers ----------------
__device__ __forceinline__ uint32_t smem_u32(const void* p) {
    uint32_t a;
    asm("{ .reg .u64 t; cvta.to.shared.u64 t, %1; cvt.u32.u64 %0, t; }" : "=r"(a) : "l"(p));
    return a;
}

#define CP_ASYNC16(saddr, gptr) \
    asm volatile("cp.async.cg.shared.global [%0], [%1], 16;" :: "r"(saddr), "l"(gptr) : "memory")
#define CP_COMMIT() asm volatile("cp.async.commit_group;" ::: "memory")
#define CP_WAIT(n)  asm volatile("cp.async.wait_group %0;" :: "n"(n) : "memory")

#define LDSM_X4(r0, r1, r2, r3, addr) \
    asm volatile("ldmatrix.sync.aligned.m8n8.x4.shared.b16 {%0,%1,%2,%3}, [%4];" \
        : "=r"(r0), "=r"(r1), "=r"(r2), "=r"(r3) : "r"(addr))

#define LDSM_X4_T(r0, r1, r2, r3, addr) \
    asm volatile("ldmatrix.sync.aligned.m8n8.x4.trans.shared.b16 {%0,%1,%2,%3}, [%4];" \
        : "=r"(r0), "=r"(r1), "=r"(r2), "=r"(r3) : "r"(addr))

#define MMA_F16(d, a, b0, b1) \
    asm volatile("mma.sync.aligned.m16n8k16.row.col.f32.f16.f16.f32 " \
        "{%0,%1,%2,%3}, {%4,%5,%6,%7}, {%8,%9}, {%0,%1,%2,%3};" \
        : "+f"((d)[0]), "+f"((d)[1]), "+f"((d)[2]), "+f"((d)[3]) \
        : "r"((a)[0]), "r"((a)[1]), "r"((a)[2]), "r"((a)[3]), "r"(b0), "r"(b1))

#define STS128(addr, u0, u1, u2, u3) \
    asm volatile("st.shared.v4.b32 [%0], {%1,%2,%3,%4};" \
        :: "r"(addr), "r"(u0), "r"(u1), "r"(u2), "r"(u3) : "memory")

__device__ __forceinline__ uint32_t swz(uint32_t off) {
    return off ^ ((off >> 3) & 0x70);
}
__device__ __forceinline__ uint32_t h2u(__half2 h) {
    return *reinterpret_cast<uint32_t*>(&h);
}

// fast gelu (tanh form): MUFU.EX2 + MUFU.RCP via __fdividef
__device__ __forceinline__ float gelu_tanh(float v) {
    float c = 0.7978845608028654f * (v + 0.044715f * v * v * v);
    float t = __expf(-2.0f * fabsf(c));
    float th = __fdividef(1.0f - t, 1.0f + t);
    th = copysignf(th, c);
    return 0.5f * v * (1.0f + th);
}

// ---------------- zero + init ----------------
__global__ __launch_bounds__(256) void zero_init_kernel(float* __restrict__ out) {
    size_t i = ((size_t)blockIdx.x * 256 + threadIdx.x) * 4;
    float4 z = {0.0f, 0.0f, 0.0f, 0.0f};
    *(float4*)(out + i) = z;
    if (blockIdx.x == 0 && threadIdx.x < E) g_counts[threadIdx.x] = 0;
}

// ---------------- router (float4-vectorized inner loop) ----------------
__global__ __launch_bounds__(256) void router_kernel(const float* __restrict__ x,
                                                     const float* __restrict__ wg) {
    __shared__ float ws[E * D];
    for (int i = threadIdx.x; i < E * D; i += 256) ws[i] = wg[i];
    __syncthreads();
    int warp = threadIdx.x >> 5, lane = threadIdx.x & 31;
    int t = blockIdx.x * 8 + warp;
    float p[E];
#pragma unroll
    for (int e = 0; e < E; e++) p[e] = 0.0f;
    const float* xr = x + (size_t)t * D;
#pragma unroll
    for (int i = lane * 4; i < D; i += 128) {
        float4 xv = *(const float4*)(xr + i);
#pragma unroll
        for (int e = 0; e < E; e++) {
            float4 wv = *(const float4*)(ws + e * D + i);
            p[e] += xv.x * wv.x + xv.y * wv.y + xv.z * wv.z + xv.w * wv.w;
        }
    }
#pragma unroll
    for (int e = 0; e < E; e++)
#pragma unroll
        for (int off = 16; off > 0; off >>= 1)
            p[e] += __shfl_down_sync(0xffffffffu, p[e], off);
    if (lane == 0) {
        float mx = p[0];
#pragma unroll
        for (int e = 1; e < E; e++) mx = fmaxf(mx, p[e]);
        float ex[E], s = 0.0f;
#pragma unroll
        for (int e = 0; e < E; e++) { ex[e] = expf(p[e] - mx); s += ex[e]; }
        float inv = 1.0f / s;
#pragma unroll
        for (int e = 0; e < E; e++) g_probs[t * E + e] = ex[e] * inv;
        int i0 = 0;
#pragma unroll
        for (int e = 1; e < E; e++) if (p[e] > p[i0]) i0 = e;
        int i1 = (i0 == 0) ? 1 : 0;
#pragma unroll
        for (int e = 0; e < E; e++) if (e != i0 && p[e] > p[i1]) i1 = e;
        float w0 = 1.0f / (1.0f + expf(p[i1] - p[i0]));
        g_tok_e[2 * t] = i0;  g_tok_e[2 * t + 1] = i1;
        g_tok_w[2 * t] = w0;  g_tok_w[2 * t + 1] = 1.0f - w0;
        atomicAdd(&g_counts[i0], 1);
        atomicAdd(&g_counts[i1], 1);
    }
}

// ---------------- setup (aux + offsets + tile list) ----------------
__global__ __launch_bounds__(256) void setup_kernel(float* __restrict__ d_out, int out_size) {
    int tid = threadIdx.x;
    float gs[E], ps[E];
#pragma unroll
    for (int e = 0; e < E; e++) { gs[e] = 0.0f; ps[e] = 0.0f; }
    for (int t = tid; t < T; t += 256) {
        gs[g_tok_e[2 * t]]     += g_tok_w[2 * t];
        gs[g_tok_e[2 * t + 1]] += g_tok_w[2 * t + 1];
#pragma unroll
        for (int e = 0; e < E; e++) ps[e] += g_probs[t * E + e];
    }
    __shared__ float red[256];
    __shared__ float gsum[E], psum[E];
    for (int e = 0; e < E; e++) {
        red[tid] = gs[e]; __syncthreads();
        for (int s = 128; s > 0; s >>= 1) { if (tid < s) red[tid] += red[tid + s]; __syncthreads(); }
        if (tid == 0) gsum[e] = red[0];
        __syncthreads();
    }
    for (int e = 0; e < E; e++) {
        red[tid] = ps[e]; __syncthreads();
        for (int s = 128; s > 0; s >>= 1) { if (tid < s) red[tid] += red[tid + s]; __syncthreads(); }
        if (tid == 0) psum[e] = red[0];
        __syncthreads();
    }
    if (tid == 0) {
        float aux = 0.0f;
        for (int e = 0; e < E; e++) aux += (gsum[e] / (float)T) * (psum[e] / (float)T);
        aux *= (float)E;
        if (out_size > T * D) d_out[T * D] = aux;
        int off = 0, nt = 0;
        for (int e = 0; e < E; e++) {
            g_offsets[e] = off;
            for (int m0 = 0; m0 < g_counts[e]; m0 += BM) { g_tile_e[nt] = e; g_tile_m0[nt] = m0; nt++; }
            off += g_counts[e];
            g_cursor[e] = 0;
        }
        g_ntiles = nt;
    }
}

// ---------------- fused scatter + gather ----------------
__global__ __launch_bounds__(256) void scatter_gather_kernel(const float* __restrict__ x) {
    int t = blockIdx.x;
    __shared__ int sp[2];
    if (threadIdx.x < 2) {
        int e = g_tok_e[2 * t + threadIdx.x];
        int p = g_offsets[e] + atomicAdd(&g_cursor[e], 1);
        g_pair_token[p] = t;
        g_pair_w[p] = g_tok_w[2 * t + threadIdx.x];
        sp[threadIdx.x] = p;
    }
    __syncthreads();
    int p0 = sp[0], p1 = sp[1];
    int c = threadIdx.x * 4;
    float4 v = *(const float4*)(x + (size_t)t * D + c);
    __half2 h0 = __floats2half2_rn(v.x, v.y);
    __half2 h1 = __floats2half2_rn(v.z, v.w);
    uint2 u;
    u.x = h2u(h0);
    u.y = h2u(h1);
    *reinterpret_cast<uint2*>(g_xa + (size_t)p0 * D + c) = u;
    *reinterpret_cast<uint2*>(g_xa + (size_t)p1 * D + c) = u;
}

// ---------------- fp16 mma.sync grouped GEMM, fp32-B converted in producer ----------------
// A: [pairs][KTOT] k-major fp16.  B: [E][KTOT][NTOT] fp32 (original weight layout).
// Smem B tile (BN=128): physical row = (n>=64)*64 + k (128 rows x 128B), ldmatrix.trans.
// CTA 256x128, BK=64, 4 stages: A via cp.async, B via LDG.128 staging + cvt + STS.
// 8 warps = 4m x 2n, warp tile 64x64.  Fragment double-buffer across ks steps.
template<int KTOT, int NTOT, bool GELU, bool ATOMIC, typename OutT>
__global__ __launch_bounds__(256, 1) void mma_gemm_kernel(
    const __half* __restrict__ Aall, const float* __restrict__ Bg,
    const float* __restrict__ bias, OutT* __restrict__ Out)
{
    int ty = blockIdx.y;
    if (ty >= g_ntiles) return;
    int e = g_tile_e[ty];
    int m0 = g_tile_m0[ty];
    int cnt = g_counts[e];
    int base = g_offsets[e];
    int n0 = blockIdx.x * BN;

    extern __shared__ char sm[];
    uint32_t sbase = smem_u32(sm);
    int tid = threadIdx.x;
    int wid = tid >> 5, lane = tid & 31;
    int warp_m = wid >> 1, warp_n = wid & 1;
    int m_base = warp_m * 64, n_base = warp_n * 64;

    const __half* Abase = Aall + (size_t)(base + m0) * KTOT;
    const float* Bbase = Bg + (size_t)e * KTOT * NTOT + n0;

    // B producer chunk mapping: 4 chunks/thread; chunk -> phys row r (0..127), 16B col cc
    int bch_r[4], bch_cc[4];
    const float* bch_g[4];
#pragma unroll
    for (int j = 0; j < 4; j++) {
        int chunk = tid + 256 * j;
        int r = chunk >> 3, cc = chunk & 7;
        bch_r[j] = r; bch_cc[j] = cc;
        int nh = r >> 6, k = r & 63;
        bch_g[j] = Bbase + (size_t)k * NTOT + nh * 64 + cc * 8;
    }

    float4 breg0[4], breg1[4];

#define LDG_B(kit) do { \
        size_t koff_ = (size_t)(kit) * BK * NTOT; \
        _Pragma("unroll") \
        for (int j_ = 0; j_ < 4; j_++) { \
            const float* gp_ = bch_g[j_] + koff_; \
            breg0[j_] = *(const float4*)gp_; \
            breg1[j_] = *(const float4*)(gp_ + 4); \
        } \
    } while (0)

#define STS_B(s) do { \
        uint32_t b_sm_ = sbase + (uint32_t)(s) * STAGE_BYTES + 32768; \
        _Pragma("unroll") \
        for (int j_ = 0; j_ < 4; j_++) { \
            uint32_t off_ = (uint32_t)(bch_r[j_] * 128 + bch_cc[j_] * 16); \
            uint32_t u0_ = h2u(__floats2half2_rn(breg0[j_].x, breg0[j_].y)); \
            uint32_t u1_ = h2u(__floats2half2_rn(breg0[j_].z, breg0[j_].w)); \
            uint32_t u2_ = h2u(__floats2half2_rn(breg1[j_].x, breg1[j_].y)); \
            uint32_t u3_ = h2u(__floats2half2_rn(breg1[j_].z, breg1[j_].w)); \
            STS128(b_sm_ + swz(off_), u0_, u1_, u2_, u3_); \
        } \
    } while (0)

#define LOAD_A(s, it) do { \
        uint32_t a_sm_ = sbase + (uint32_t)(s) * STAGE_BYTES; \
        int k0_ = (it) * BK; \
        _Pragma("unroll") \
        for (int j_ = 0; j_ < 8; j_++) { \
            int chunk_ = tid + 256 * j_; \
            int row_ = chunk_ >> 3, cc_ = chunk_ & 7; \
            uint32_t off_ = (uint32_t)(row_ * 128 + cc_ * 16); \
            CP_ASYNC16(a_sm_ + swz(off_), Abase + (size_t)row_ * KTOT + k0_ + cc_ * 8); \
        } \
    } while (0)

// load fragments for step ks into buffer slot bb
#define LOAD_FRAGS(bb, ks) do { \
        _Pragma("unroll") \
        for (int mt_ = 0; mt_ < 4; mt_++) { \
            uint32_t off_ = (uint32_t)((m_base + mt_ * 16 + lrow) * 128) + (ks) * 32 + lkhi; \
            LDSM_X4(af[bb][mt_][0], af[bb][mt_][1], af[bb][mt_][2], af[bb][mt_][3], \
                    a_sm + swz(off_)); \
        } \
        _Pragma("unroll") \
        for (int np_ = 0; np_ < 4; np_++) { \
            LDSM_X4_T(bf[bb][np_][0], bf[bb][np_][1], bf[bb][np_][2], bf[bb][np_][3], \
                      b_sm + soffB[np_] + (uint32_t)((ks) * 2048)); \
        } \
    } while (0)

    float acc[4][8][4];
#pragma unroll
    for (int i = 0; i < 4; i++)
#pragma unroll
        for (int j = 0; j < 8; j++)
#pragma unroll
            for (int k = 0; k < 4; k++) acc[i][j][k] = 0.0f;

    const int KITERS = KTOT / BK;

    // prologue: fill stages 0..S-2 (B direct LDG+STS, A cp.async)
#pragma unroll
    for (int s = 0; s < STAGES - 1; s++) {
        LDG_B(s);
        STS_B(s);
        LOAD_A(s, s);
        CP_COMMIT();
    }
    // preload B regs for stage S-1 (stored at iter 0)
    LDG_B(STAGES - 1);

    // B ldmatrix.trans swizzled base offsets (per lane, per n16-block)
    int gq = lane >> 3, l7 = lane & 7;
    uint32_t soffB[4];
#pragma unroll
    for (int np = 0; np < 4; np++) {
        int nl = n_base + np * 16 + (gq & 1) * 8;
        int klow = (gq >> 1) * 8 + l7;
        uint32_t boff = (uint32_t)((((nl >> 6) * 64) + klow) * 128 + (nl & 63) * 2);
        soffB[np] = swz(boff);
    }

    int lrow = lane & 15;
    uint32_t lkhi = (uint32_t)((lane >> 4) * 16);

    uint32_t af[2][4][4], bf[2][4][4];

    for (int it = 0; it < KITERS; ++it) {
        CP_WAIT(STAGES - 2);
        __syncthreads();

        int refill = it + STAGES - 1;
        if (refill < KITERS) {
            int rs = refill % STAGES;
            STS_B(rs);
            LOAD_A(rs, refill);
        }
        CP_COMMIT();
        if (it + STAGES < KITERS) LDG_B(it + STAGES);

        uint32_t a_sm = sbase + (uint32_t)(it % STAGES) * STAGE_BYTES;
        uint32_t b_sm = a_sm + 32768;

        LOAD_FRAGS(0, 0);
#pragma unroll
        for (int ks = 0; ks < 4; ks++) {   // 4 x k16 per BK=64
            if (ks < 3) LOAD_FRAGS((ks + 1) & 1, ks + 1);
            const int cb = ks & 1;
#pragma unroll
            for (int mt = 0; mt < 4; mt++)
#pragma unroll
                for (int nt = 0; nt < 8; nt++)
                    MMA_F16(acc[mt][nt], af[cb][mt],
                            bf[cb][nt >> 1][nt & 1], bf[cb][nt >> 1][(nt & 1) + 2]);
        }
    }

    // ---- epilogue ----
    int rq = lane >> 2;
    int cq = (lane & 3) * 2;
#pragma unroll
    for (int mt = 0; mt < 4; mt++) {
#pragma unroll
        for (int h = 0; h < 2; h++) {
            int row = m_base + mt * 16 + h * 8 + rq;
            int m = m0 + row;
            if (m >= cnt) continue;
            if (ATOMIC) {
                // GEMM2: y[tok] += w * (acc + b2[e])
                int P = base + m;
                int tok = g_pair_token[P];
                float w = g_pair_w[P];
                float* orow = (float*)Out + (size_t)tok * NTOT;
                const float* bp = bias + (size_t)e * NTOT;
#pragma unroll
                for (int nt = 0; nt < 8; nt++) {
                    int col = n0 + n_base + nt * 8 + cq;
                    atomicAdd(&orow[col],     w * (acc[mt][nt][h * 2 + 0] + bp[col]));
                    atomicAdd(&orow[col + 1], w * (acc[mt][nt][h * 2 + 1] + bp[col + 1]));
                }
            } else {
                OutT* orow = Out + (size_t)(base + m) * NTOT + n0;
#pragma unroll
                for (int nt = 0; nt < 8; nt++) {
                    int col = n_base + nt * 8 + cq;
                    float v0 = acc[mt][nt][h * 2 + 0];
                    float v1 = acc[mt][nt][h * 2 + 1];
                    if (GELU) {
                        const float* bp = bias + (size_t)e * NTOT + n0 + col;
                        v0 = gelu_tanh(v0 + bp[0]);
                        v1 = gelu_tanh(v1 + bp[1]);
                    }
                    __half2 hv = __floats2half2_rn(v0, v1);
                    *reinterpret_cast<__half2*>((__half*)orow + col) = hv;
                }
            }
        }
    }
#undef LDG_B
#undef STS_B
#undef LOAD_A
#undef LOAD_FRAGS
}

// ---------------- launch ----------------
extern "C" void kernel_launch(void* const* d_in, const int* in_sizes, int n_in,
                              void* d_out, int out_size) {
    const float* x  = (const float*)d_in[0];
    const float* wg = (const float*)d_in[1];
    const float* W1 = (const float*)d_in[2];
    const float* b1 = (const float*)d_in[3];
    const float* W2 = (const float*)d_in[4];
    const float* b2 = (const float*)d_in[5];
    float* out = (float*)d_out;

    cudaFuncSetAttribute(mma_gemm_kernel<D, HDIM, true, false, __half>,
                         cudaFuncAttributeMaxDynamicSharedMemorySize, SMEM_DYN);
    cudaFuncSetAttribute(mma_gemm_kernel<HDIM, D, false, true, float>,
                         cudaFuncAttributeMaxDynamicSharedMemorySize, SMEM_DYN);

    __half* xa;  cudaGetSymbolAddress((void**)&xa, g_xa);
    __half* gh;  cudaGetSymbolAddress((void**)&gh, g_h);

    zero_init_kernel<<<(T * D / 4) / 256, 256>>>(out);
    router_kernel<<<T / 8, 256>>>(x, wg);
    setup_kernel<<<1, 256>>>(out, out_size);
    scatter_gather_kernel<<<T, 256>>>(x);
    mma_gemm_kernel<D, HDIM, true, false, __half>
        <<<dim3(HDIM / BN, MAXTILES), 256, SMEM_DYN>>>(xa, W1, b1, gh);
    mma_gemm_kernel<HDIM, D, false, true, float>
        <<<dim3(D / BN, MAXTILES), 256, SMEM_DYN>>>(gh, W2, b2, out);
}